// round 1
// baseline (speedup 1.0000x reference)
#include <cuda_runtime.h>
#include <cstdint>
#include <cstddef>

// Problem constants (from reference_code)
#define N_NODES 100000
#define N_EDGES 300000
#define F_IN_DIM 128
#define H_DIM 256
#define L_NUM 3

// ---------------------------------------------------------------------------
// Scratch (allocation-free): three N x H fp32 ping-pong buffers + degree/norm
// ---------------------------------------------------------------------------
__device__ float g_bufA[(size_t)N_NODES * H_DIM];
__device__ float g_bufB[(size_t)N_NODES * H_DIM];
__device__ float g_bufM[(size_t)N_NODES * H_DIM];
__device__ int   g_deg[N_NODES];
__device__ float g_dinv[N_NODES];

// ---------------------------------------------------------------------------
// Degree / normalization
// ---------------------------------------------------------------------------
__global__ void deg_init_kernel(int* __restrict__ deg, int n) {
    int i = blockIdx.x * blockDim.x + threadIdx.x;
    if (i < n) deg[i] = 1;  // self-loop
}

__global__ void deg_edge_kernel(const int* __restrict__ dst, int* __restrict__ deg, int e) {
    int i = blockIdx.x * blockDim.x + threadIdx.x;
    if (i < e) atomicAdd(&deg[dst[i]], 1);
}

__global__ void dinv_kernel(const int* __restrict__ deg, float* __restrict__ dinv, int n) {
    int i = blockIdx.x * blockDim.x + threadIdx.x;
    if (i < n) dinv[i] = rsqrtf((float)deg[i]);
}

// ---------------------------------------------------------------------------
// Tiled SGEMM: C[M,256] = op(A)[M,K] @ W[K,256] (+ bias)
// op(A) = relu(A) if RELU_A. BM=128, BN=128, BK=8, 256 threads, 8x8 per thread
// ---------------------------------------------------------------------------
template<bool RELU_A, bool HAS_BIAS>
__global__ __launch_bounds__(256)
void gemm128_kernel(const float* __restrict__ A, const float* __restrict__ W,
                    const float* __restrict__ bias, float* __restrict__ C,
                    int M_rows, int K) {
    __shared__ float As[8][128];   // transposed: As[k][m]
    __shared__ float Ws[8][128];   // Ws[k][n]

    const int tid = threadIdx.x;
    const int block_row = blockIdx.x * 128;
    const int block_col = blockIdx.y * 128;

    // Global-load mapping
    const int a_row = tid >> 1;            // 0..127
    const int a_col = (tid & 1) << 2;      // 0 or 4
    const int w_row = tid >> 5;            // 0..7
    const int w_col = (tid & 31) << 2;     // 0..124

    // Compute-tile mapping: 16 (n) x 16 (m) threads, each 8x8
    const int tn = (tid & 15) << 3;        // col offset in tile
    const int tm = (tid >> 4) << 3;        // row offset in tile

    float acc[8][8];
#pragma unroll
    for (int i = 0; i < 8; i++)
#pragma unroll
        for (int j = 0; j < 8; j++) acc[i][j] = 0.f;

    const int gr_a = block_row + a_row;
    const bool a_ok = (gr_a < M_rows);

    for (int k0 = 0; k0 < K; k0 += 8) {
        float4 av = make_float4(0.f, 0.f, 0.f, 0.f);
        if (a_ok) av = *(const float4*)(A + (size_t)gr_a * K + k0 + a_col);
        if (RELU_A) {
            av.x = fmaxf(av.x, 0.f); av.y = fmaxf(av.y, 0.f);
            av.z = fmaxf(av.z, 0.f); av.w = fmaxf(av.w, 0.f);
        }
        float4 wv = *(const float4*)(W + (size_t)(k0 + w_row) * H_DIM + block_col + w_col);

        As[a_col + 0][a_row] = av.x;
        As[a_col + 1][a_row] = av.y;
        As[a_col + 2][a_row] = av.z;
        As[a_col + 3][a_row] = av.w;
        *(float4*)&Ws[w_row][w_col] = wv;
        __syncthreads();

#pragma unroll
        for (int k = 0; k < 8; k++) {
            float4 a0 = *(const float4*)&As[k][tm];
            float4 a1 = *(const float4*)&As[k][tm + 4];
            float4 b0 = *(const float4*)&Ws[k][tn];
            float4 b1 = *(const float4*)&Ws[k][tn + 4];
            float af[8] = {a0.x, a0.y, a0.z, a0.w, a1.x, a1.y, a1.z, a1.w};
            float bf[8] = {b0.x, b0.y, b0.z, b0.w, b1.x, b1.y, b1.z, b1.w};
#pragma unroll
            for (int i = 0; i < 8; i++)
#pragma unroll
                for (int j = 0; j < 8; j++)
                    acc[i][j] = fmaf(af[i], bf[j], acc[i][j]);
        }
        __syncthreads();
    }

    float bv[8];
#pragma unroll
    for (int j = 0; j < 8; j++)
        bv[j] = HAS_BIAS ? bias[block_col + tn + j] : 0.f;

#pragma unroll
    for (int i = 0; i < 8; i++) {
        int gr = block_row + tm + i;
        if (gr < M_rows) {
            float4 o0, o1;
            o0.x = acc[i][0] + bv[0]; o0.y = acc[i][1] + bv[1];
            o0.z = acc[i][2] + bv[2]; o0.w = acc[i][3] + bv[3];
            o1.x = acc[i][4] + bv[4]; o1.y = acc[i][5] + bv[5];
            o1.z = acc[i][6] + bv[6]; o1.w = acc[i][7] + bv[7];
            float* cp = C + (size_t)gr * H_DIM + block_col + tn;
            *(float4*)(cp)     = o0;
            *(float4*)(cp + 4) = o1;
        }
    }
}

// ---------------------------------------------------------------------------
// Scatter: out[i,:] = bias + m[i,:]*dinv[i]^2 (self-loop + bias init)
// then edge kernel: out[dst,:] += m[src,:]*dinv[src]*dinv[dst]
// ---------------------------------------------------------------------------
__global__ void scatter_init_kernel(const float* __restrict__ m, const float* __restrict__ bias,
                                    const float* __restrict__ dinv, float* __restrict__ out,
                                    int n) {
    int i = blockIdx.x * blockDim.x + threadIdx.x;      // one float4 / thread
    int total = n * (H_DIM / 4);
    if (i >= total) return;
    int row = i / (H_DIM / 4);
    int c4  = i - row * (H_DIM / 4);
    float di = dinv[row];
    float w = di * di;
    float4 mv = ((const float4*)m)[i];
    float4 bv = ((const float4*)bias)[c4];
    float4 o;
    o.x = fmaf(mv.x, w, bv.x);
    o.y = fmaf(mv.y, w, bv.y);
    o.z = fmaf(mv.z, w, bv.z);
    o.w = fmaf(mv.w, w, bv.w);
    ((float4*)out)[i] = o;
}

__device__ __forceinline__ void red_add_v4(float* p, float4 v) {
    asm volatile("red.global.add.v4.f32 [%0], {%1,%2,%3,%4};"
                 :: "l"(p), "f"(v.x), "f"(v.y), "f"(v.z), "f"(v.w) : "memory");
}

__global__ __launch_bounds__(256)
void scatter_edge_kernel(const float* __restrict__ m, float* __restrict__ out,
                         const int* __restrict__ src, const int* __restrict__ dst,
                         const float* __restrict__ dinv, int E) {
    int g = blockIdx.x * blockDim.x + threadIdx.x;
    int e = g >> 5;
    int lane = g & 31;
    if (e >= E) return;
    int s = __ldg(&src[e]);
    int d = __ldg(&dst[e]);
    float w = dinv[s] * dinv[d];
    const float4* mr = (const float4*)(m + (size_t)s * H_DIM);
    float* orow = out + (size_t)d * H_DIM;
    float4 v0 = mr[lane];
    float4 v1 = mr[lane + 32];
    v0.x *= w; v0.y *= w; v0.z *= w; v0.w *= w;
    v1.x *= w; v1.y *= w; v1.z *= w; v1.w *= w;
    red_add_v4(orow + lane * 4, v0);
    red_add_v4(orow + (lane + 32) * 4, v1);
}

__global__ void relu_inplace_kernel(float* __restrict__ p, int total4) {
    int i = blockIdx.x * blockDim.x + threadIdx.x;
    if (i >= total4) return;
    float4 v = ((float4*)p)[i];
    v.x = fmaxf(v.x, 0.f); v.y = fmaxf(v.y, 0.f);
    v.z = fmaxf(v.z, 0.f); v.w = fmaxf(v.w, 0.f);
    ((float4*)p)[i] = v;
}

// ---------------------------------------------------------------------------
// Launch
// ---------------------------------------------------------------------------
extern "C" void kernel_launch(void* const* d_in, const int* in_sizes, int n_in,
                              void* d_out, int out_size) {
    const float* x   = (const float*)d_in[0];
    const int*   ei  = (const int*)d_in[1];
    const float* w1  = (const float*)d_in[2];
    const float* b1  = (const float*)d_in[3];
    const float* w2  = (const float*)d_in[4];
    const float* b2  = (const float*)d_in[5];
    const float* gw  = (const float*)d_in[6];
    const float* gb  = (const float*)d_in[7];

    const int N = N_NODES;
    const int E = N_EDGES;
    const int* srcp = ei;
    const int* dstp = ei + E;

    float *bufA, *bufB, *bufM, *dinv;
    int* deg;
    cudaGetSymbolAddress((void**)&bufA, g_bufA);
    cudaGetSymbolAddress((void**)&bufB, g_bufB);
    cudaGetSymbolAddress((void**)&bufM, g_bufM);
    cudaGetSymbolAddress((void**)&dinv, g_dinv);
    cudaGetSymbolAddress((void**)&deg,  g_deg);

    float* out = (float*)d_out;

    // 1) degrees + normalization
    deg_init_kernel<<<(N + 255) / 256, 256>>>(deg, N);
    deg_edge_kernel<<<(E + 255) / 256, 256>>>(dstp, deg, E);
    dinv_kernel<<<(N + 255) / 256, 256>>>(deg, dinv, N);

    dim3 ggrid((N + 127) / 128, H_DIM / 128);
    const int elem4 = N * (H_DIM / 4);
    const int egrid = (E * 32 + 255) / 256;

    // 2) encoder: bufA = x@w1+b1 ; bufB = relu(bufA)@w2+b2
    gemm128_kernel<false, true><<<ggrid, 256>>>(x, w1, b1, bufA, N, F_IN_DIM);
    gemm128_kernel<true,  true><<<ggrid, 256>>>(bufA, w2, b2, bufB, N, H_DIM);

    // 3) GCN layers. h buffers: l0: bufB -> bufA, l1: bufA -> bufB, l2: bufB -> out
    // ReLU is deferred: stored pre-relu, applied on next GEMM's A-read (or final pass).
    // l = 0 (input has no pending relu)
    gemm128_kernel<false, false><<<ggrid, 256>>>(bufB, gw + 0 * H_DIM * H_DIM, nullptr, bufM, N, H_DIM);
    scatter_init_kernel<<<(elem4 + 255) / 256, 256>>>(bufM, gb + 0 * H_DIM, dinv, bufA, N);
    scatter_edge_kernel<<<egrid, 256>>>(bufM, bufA, srcp, dstp, dinv, E);
    // l = 1
    gemm128_kernel<true, false><<<ggrid, 256>>>(bufA, gw + 1 * H_DIM * H_DIM, nullptr, bufM, N, H_DIM);
    scatter_init_kernel<<<(elem4 + 255) / 256, 256>>>(bufM, gb + 1 * H_DIM, dinv, bufB, N);
    scatter_edge_kernel<<<egrid, 256>>>(bufM, bufB, srcp, dstp, dinv, E);
    // l = 2 -> d_out
    gemm128_kernel<true, false><<<ggrid, 256>>>(bufB, gw + 2 * H_DIM * H_DIM, nullptr, bufM, N, H_DIM);
    scatter_init_kernel<<<(elem4 + 255) / 256, 256>>>(bufM, gb + 2 * H_DIM, dinv, out, N);
    scatter_edge_kernel<<<egrid, 256>>>(bufM, out, srcp, dstp, dinv, E);

    // final ReLU in-place on output
    relu_inplace_kernel<<<(elem4 + 255) / 256, 256>>>(out, elem4);
}

// round 5
// speedup vs baseline: 1.8646x; 1.8646x over previous
#include <cuda_runtime.h>
#include <cuda_fp16.h>
#include <cstdint>
#include <cstddef>

// Problem constants
#define NN  100000
#define EE  300000
#define FIN 128
#define HD  256

// ---------------------------------------------------------------------------
// Scratch (allocation-free)
// ---------------------------------------------------------------------------
__device__ float g_bufA[(size_t)NN * HD];
__device__ float g_bufB[(size_t)NN * HD];
__device__ float g_bufM[(size_t)NN * HD];
__device__ int   g_deg[NN];
__device__ float g_dinv[NN];
// Pre-transposed ([N,K]) fp16-split weights
__device__ __half g_w1h[HD * FIN], g_w1l[HD * FIN];
__device__ __half g_w2h[HD * HD],  g_w2l[HD * HD];
__device__ __half g_gwh[3 * HD * HD], g_gwl[3 * HD * HD];

// ---------------------------------------------------------------------------
// Helpers
// ---------------------------------------------------------------------------
static __device__ __forceinline__ uint32_t s2u(const void* p) {
    uint32_t a;
    asm("{ .reg .u64 t; cvta.to.shared.u64 t, %1; cvt.u32.u64 %0, t; }" : "=r"(a) : "l"(p));
    return a;
}

static __device__ __forceinline__ void fsplit(float v, __half& h, __half& l) {
    h = __float2half_rn(v);
    l = __float2half_rn(v - __half2float(h));
}

#define LDSM4(R, addr) \
    asm volatile("ldmatrix.sync.aligned.m8n8.x4.shared.b16 {%0,%1,%2,%3}, [%4];" \
                 : "=r"((R)[0]), "=r"((R)[1]), "=r"((R)[2]), "=r"((R)[3]) : "r"(addr))

#define LDSM2(R, addr) \
    asm volatile("ldmatrix.sync.aligned.m8n8.x2.shared.b16 {%0,%1}, [%2];" \
                 : "=r"((R)[0]), "=r"((R)[1]) : "r"(addr))

#define MMA16816(C, A, B) \
    asm volatile("mma.sync.aligned.m16n8k16.row.col.f32.f16.f16.f32 " \
                 "{%0,%1,%2,%3},{%4,%5,%6,%7},{%8,%9},{%0,%1,%2,%3};" \
                 : "+f"((C)[0]), "+f"((C)[1]), "+f"((C)[2]), "+f"((C)[3]) \
                 : "r"((A)[0]), "r"((A)[1]), "r"((A)[2]), "r"((A)[3]), \
                   "r"((B)[0]), "r"((B)[1]))

// SMEM geometry (halves). Row stride 40 halves (80B) -> conflict-free ldmatrix.
#define SA 40
#define OFF_AH 0
#define OFF_AL 5120
#define OFF_BH 10240
#define OFF_BL 15360
#define STAGE_H 20480
#define SMEM_BYTES (2 * STAGE_H * 2)

// ---------------------------------------------------------------------------
// fp16x2-split (3-product) tensor-core GEMM:
// C[M,256] = op(A)[M,K] @ Bt[N,K]^T (+bias), op = relu if RELU_A.
// BM=128, BN=128, BK=32, 256 threads. Warps: 2(m) x 4(n); warp tile 64x32.
// ---------------------------------------------------------------------------
template<bool RELU_A, bool HAS_BIAS>
__global__ __launch_bounds__(256)
void hgemm_kernel(const float* __restrict__ A, const __half* __restrict__ BHp,
                  const __half* __restrict__ BLp, const float* __restrict__ bias,
                  float* __restrict__ C, int M_rows, int K) {
    extern __shared__ __half sh[];
    const int tid  = threadIdx.x;
    const int lane = tid & 31;
    const int wid  = tid >> 5;
    const int wm   = wid & 1;       // 0..1 : 64 rows each
    const int wn   = wid >> 1;      // 0..3 : 32 cols each
    const int block_row = blockIdx.x * 128;
    const int n0        = blockIdx.y * 128;

    float acc[4][4][4];
#pragma unroll
    for (int mt = 0; mt < 4; mt++)
#pragma unroll
        for (int nt = 0; nt < 4; nt++)
#pragma unroll
            for (int j = 0; j < 4; j++) acc[mt][nt][j] = 0.f;

    const int NC = K >> 5;          // chunks of 32

    // Per-thread load coordinates
    const int ar = tid >> 3;                // A row base
    const int ak = (tid & 7) << 2;          // A col group (fp32 x4)
    const int br = tid >> 2;                // B row base
    const int bk = (tid & 3) << 3;          // B col group (half x8)

    float4 apf[4];
    uint4  bhpf[2], blpf[2];

#define LOAD_PF(c)                                                              \
    {                                                                           \
        const int k0 = (c) << 5;                                                \
        _Pragma("unroll")                                                       \
        for (int i = 0; i < 4; i++) {                                           \
            int row = ar + (i << 5);                                            \
            int gr = block_row + row;                                           \
            if (gr < M_rows)                                                    \
                apf[i] = *(const float4*)(A + (size_t)gr * K + k0 + ak);        \
            else                                                                \
                apf[i] = make_float4(0.f, 0.f, 0.f, 0.f);                       \
        }                                                                       \
        _Pragma("unroll")                                                       \
        for (int i = 0; i < 2; i++) {                                           \
            int row = br + (i << 6);                                            \
            size_t g = (size_t)(n0 + row) * K + k0 + bk;                        \
            bhpf[i] = *(const uint4*)(BHp + g);                                 \
            blpf[i] = *(const uint4*)(BLp + g);                                 \
        }                                                                       \
    }

#define STORE_PF(soff)                                                          \
    {                                                                           \
        _Pragma("unroll")                                                       \
        for (int i = 0; i < 4; i++) {                                           \
            int row = ar + (i << 5);                                            \
            float4 v = apf[i];                                                  \
            if (RELU_A) {                                                       \
                v.x = fmaxf(v.x, 0.f); v.y = fmaxf(v.y, 0.f);                   \
                v.z = fmaxf(v.z, 0.f); v.w = fmaxf(v.w, 0.f);                   \
            }                                                                   \
            __half h0, h1, h2, h3, l0, l1, l2, l3;                              \
            fsplit(v.x, h0, l0); fsplit(v.y, h1, l1);                           \
            fsplit(v.z, h2, l2); fsplit(v.w, h3, l3);                           \
            __half* ph = sh + (soff) + OFF_AH + row * SA + ak;                  \
            __half* pl = sh + (soff) + OFF_AL + row * SA + ak;                  \
            *(__half2*)(ph)     = __halves2half2(h0, h1);                       \
            *(__half2*)(ph + 2) = __halves2half2(h2, h3);                       \
            *(__half2*)(pl)     = __halves2half2(l0, l1);                       \
            *(__half2*)(pl + 2) = __halves2half2(l2, l3);                       \
        }                                                                       \
        _Pragma("unroll")                                                       \
        for (int i = 0; i < 2; i++) {                                           \
            int row = br + (i << 6);                                            \
            *(uint4*)(sh + (soff) + OFF_BH + row * SA + bk) = bhpf[i];          \
            *(uint4*)(sh + (soff) + OFF_BL + row * SA + bk) = blpf[i];          \
        }                                                                       \
    }

    LOAD_PF(0);
    STORE_PF(0);
    __syncthreads();

    for (int c = 0; c < NC; c++) {
        const int soff = (c & 1) * STAGE_H;
        if (c + 1 < NC) LOAD_PF(c + 1);

        // --- MMA on stage soff ---
#pragma unroll
        for (int s = 0; s < 2; s++) {
            uint32_t ah[4][4], al[4][4];
#pragma unroll
            for (int mt = 0; mt < 4; mt++) {
                int row = wm * 64 + mt * 16 + (lane & 15);
                int col = s * 16 + ((lane >> 4) << 3);
                uint32_t ad = s2u(sh + soff + OFF_AH + row * SA + col);
                LDSM4(ah[mt], ad);
                LDSM4(al[mt], ad + OFF_AL * 2);
            }
#pragma unroll
            for (int nt = 0; nt < 4; nt++) {
                int row = wn * 32 + nt * 8 + (lane & 7);
                int col = s * 16 + (((lane >> 3) & 1) << 3);
                uint32_t bd = s2u(sh + soff + OFF_BH + row * SA + col);
                uint32_t bh[2], bl[2];
                LDSM2(bh, bd);
                LDSM2(bl, bd + (OFF_BL - OFF_BH) * 2);
#pragma unroll
                for (int mt = 0; mt < 4; mt++) MMA16816(acc[mt][nt], ah[mt], bh);
#pragma unroll
                for (int mt = 0; mt < 4; mt++) MMA16816(acc[mt][nt], al[mt], bh);
#pragma unroll
                for (int mt = 0; mt < 4; mt++) MMA16816(acc[mt][nt], ah[mt], bl);
            }
        }

        if (c + 1 < NC) {
            STORE_PF(((c + 1) & 1) * STAGE_H);
            __syncthreads();
        }
    }

    // Epilogue
    const int qm = lane >> 2;          // row within tile
    const int qn = (lane & 3) << 1;    // col pair within n8
#pragma unroll
    for (int mt = 0; mt < 4; mt++) {
#pragma unroll
        for (int nt = 0; nt < 4; nt++) {
            int nc = n0 + wn * 32 + nt * 8 + qn;
            float b0 = 0.f, b1 = 0.f;
            if (HAS_BIAS) { b0 = bias[nc]; b1 = bias[nc + 1]; }
            int gr0 = block_row + wm * 64 + mt * 16 + qm;
            if (gr0 < M_rows) {
                float2 o = make_float2(acc[mt][nt][0] + b0, acc[mt][nt][1] + b1);
                *(float2*)(C + (size_t)gr0 * HD + nc) = o;
            }
            int gr1 = gr0 + 8;
            if (gr1 < M_rows) {
                float2 o = make_float2(acc[mt][nt][2] + b0, acc[mt][nt][3] + b1);
                *(float2*)(C + (size_t)gr1 * HD + nc) = o;
            }
        }
    }
#undef LOAD_PF
#undef STORE_PF
}

// ---------------------------------------------------------------------------
// Weight transpose + fp16 split: W[K,N] -> Wt_hi/lo[N,K]
// ---------------------------------------------------------------------------
__global__ void wsplit_kernel(const float* __restrict__ W, __half* __restrict__ hi,
                              __half* __restrict__ lo, int K, int N) {
    int i = blockIdx.x * blockDim.x + threadIdx.x;
    if (i >= K * N) return;
    int k = i / N, n = i - k * N;
    __half h, l;
    fsplit(W[i], h, l);
    hi[(size_t)n * K + k] = h;
    lo[(size_t)n * K + k] = l;
}

// ---------------------------------------------------------------------------
// Degree / normalization
// ---------------------------------------------------------------------------
__global__ void deg_init_kernel(int* __restrict__ deg, int n) {
    int i = blockIdx.x * blockDim.x + threadIdx.x;
    if (i < n) deg[i] = 1;
}
__global__ void deg_edge_kernel(const int* __restrict__ dst, int* __restrict__ deg, int e) {
    int i = blockIdx.x * blockDim.x + threadIdx.x;
    if (i < e) atomicAdd(&deg[dst[i]], 1);
}
__global__ void dinv_kernel(const int* __restrict__ deg, float* __restrict__ dinv, int n) {
    int i = blockIdx.x * blockDim.x + threadIdx.x;
    if (i < n) dinv[i] = rsqrtf((float)deg[i]);
}

// ---------------------------------------------------------------------------
// Scatter
// ---------------------------------------------------------------------------
__global__ void scatter_init_kernel(const float* __restrict__ m, const float* __restrict__ bias,
                                    const float* __restrict__ dinv, float* __restrict__ out,
                                    int n) {
    int i = blockIdx.x * blockDim.x + threadIdx.x;
    int total = n * (HD / 4);
    if (i >= total) return;
    int row = i / (HD / 4);
    int c4  = i - row * (HD / 4);
    float di = dinv[row];
    float w = di * di;
    float4 mv = ((const float4*)m)[i];
    float4 bv = ((const float4*)bias)[c4];
    float4 o;
    o.x = fmaf(mv.x, w, bv.x);
    o.y = fmaf(mv.y, w, bv.y);
    o.z = fmaf(mv.z, w, bv.z);
    o.w = fmaf(mv.w, w, bv.w);
    ((float4*)out)[i] = o;
}

__device__ __forceinline__ void red_add_v4(float* p, float4 v) {
    asm volatile("red.global.add.v4.f32 [%0], {%1,%2,%3,%4};"
                 :: "l"(p), "f"(v.x), "f"(v.y), "f"(v.z), "f"(v.w) : "memory");
}

__global__ __launch_bounds__(256)
void scatter_edge_kernel(const float* __restrict__ m, float* __restrict__ out,
                         const int* __restrict__ src, const int* __restrict__ dst,
                         const float* __restrict__ dinv, int E) {
    int g = blockIdx.x * blockDim.x + threadIdx.x;
    int e = g >> 5;
    int lane = g & 31;
    if (e >= E) return;
    int s = __ldg(&src[e]);
    int d = __ldg(&dst[e]);
    float w = dinv[s] * dinv[d];
    const float4* mr = (const float4*)(m + (size_t)s * HD);
    float* orow = out + (size_t)d * HD;
    float4 v0 = mr[lane];
    float4 v1 = mr[lane + 32];
    v0.x *= w; v0.y *= w; v0.z *= w; v0.w *= w;
    v1.x *= w; v1.y *= w; v1.z *= w; v1.w *= w;
    red_add_v4(orow + lane * 4, v0);
    red_add_v4(orow + (lane + 32) * 4, v1);
}

__global__ void relu_inplace_kernel(float* __restrict__ p, int total4) {
    int i = blockIdx.x * blockDim.x + threadIdx.x;
    if (i >= total4) return;
    float4 v = ((float4*)p)[i];
    v.x = fmaxf(v.x, 0.f); v.y = fmaxf(v.y, 0.f);
    v.z = fmaxf(v.z, 0.f); v.w = fmaxf(v.w, 0.f);
    ((float4*)p)[i] = v;
}

// ---------------------------------------------------------------------------
// Launch
// ---------------------------------------------------------------------------
extern "C" void kernel_launch(void* const* d_in, const int* in_sizes, int n_in,
                              void* d_out, int out_size) {
    const float* x  = (const float*)d_in[0];
    const int*   ei = (const int*)d_in[1];
    const float* w1 = (const float*)d_in[2];
    const float* b1 = (const float*)d_in[3];
    const float* w2 = (const float*)d_in[4];
    const float* b2 = (const float*)d_in[5];
    const float* gw = (const float*)d_in[6];
    const float* gb = (const float*)d_in[7];

    const int N = NN;
    const int E = EE;
    const int* srcp = ei;
    const int* dstp = ei + E;

    float *bufA, *bufB, *bufM, *dinv;
    __half *w1h, *w1l, *w2h, *w2l, *gwh, *gwl;
    int* deg;
    cudaGetSymbolAddress((void**)&bufA, g_bufA);
    cudaGetSymbolAddress((void**)&bufB, g_bufB);
    cudaGetSymbolAddress((void**)&bufM, g_bufM);
    cudaGetSymbolAddress((void**)&dinv, g_dinv);
    cudaGetSymbolAddress((void**)&deg,  g_deg);
    cudaGetSymbolAddress((void**)&w1h,  g_w1h);
    cudaGetSymbolAddress((void**)&w1l,  g_w1l);
    cudaGetSymbolAddress((void**)&w2h,  g_w2h);
    cudaGetSymbolAddress((void**)&w2l,  g_w2l);
    cudaGetSymbolAddress((void**)&gwh,  g_gwh);
    cudaGetSymbolAddress((void**)&gwl,  g_gwl);

    float* out = (float*)d_out;

    cudaFuncSetAttribute(hgemm_kernel<false, true>,
                         cudaFuncAttributeMaxDynamicSharedMemorySize, SMEM_BYTES);
    cudaFuncSetAttribute(hgemm_kernel<true, true>,
                         cudaFuncAttributeMaxDynamicSharedMemorySize, SMEM_BYTES);
    cudaFuncSetAttribute(hgemm_kernel<false, false>,
                         cudaFuncAttributeMaxDynamicSharedMemorySize, SMEM_BYTES);
    cudaFuncSetAttribute(hgemm_kernel<true, false>,
                         cudaFuncAttributeMaxDynamicSharedMemorySize, SMEM_BYTES);

    // Weight transpose + split (tiny)
    wsplit_kernel<<<(FIN * HD + 255) / 256, 256>>>(w1, w1h, w1l, FIN, HD);
    wsplit_kernel<<<(HD * HD + 255) / 256, 256>>>(w2, w2h, w2l, HD, HD);
    for (int l = 0; l < 3; l++)
        wsplit_kernel<<<(HD * HD + 255) / 256, 256>>>(gw + (size_t)l * HD * HD,
                                                      gwh + (size_t)l * HD * HD,
                                                      gwl + (size_t)l * HD * HD, HD, HD);

    // degrees + normalization
    deg_init_kernel<<<(N + 255) / 256, 256>>>(deg, N);
    deg_edge_kernel<<<(E + 255) / 256, 256>>>(dstp, deg, E);
    dinv_kernel<<<(N + 255) / 256, 256>>>(deg, dinv, N);

    dim3 ggrid((N + 127) / 128, HD / 128);
    const int elem4 = N * (HD / 4);
    const int egrid = (E * 32 + 255) / 256;

    // encoder
    hgemm_kernel<false, true><<<ggrid, 256, SMEM_BYTES>>>(x, w1h, w1l, b1, bufA, N, FIN);
    hgemm_kernel<true,  true><<<ggrid, 256, SMEM_BYTES>>>(bufA, w2h, w2l, b2, bufB, N, HD);

    // GCN layer 0: bufB -> bufA
    hgemm_kernel<false, false><<<ggrid, 256, SMEM_BYTES>>>(bufB, gwh, gwl, nullptr, bufM, N, HD);
    scatter_init_kernel<<<(elem4 + 255) / 256, 256>>>(bufM, gb + 0 * HD, dinv, bufA, N);
    scatter_edge_kernel<<<egrid, 256>>>(bufM, bufA, srcp, dstp, dinv, E);
    // layer 1: bufA -> bufB (deferred relu on A)
    hgemm_kernel<true, false><<<ggrid, 256, SMEM_BYTES>>>(bufA, gwh + HD * HD, gwl + HD * HD,
                                                          nullptr, bufM, N, HD);
    scatter_init_kernel<<<(elem4 + 255) / 256, 256>>>(bufM, gb + 1 * HD, dinv, bufB, N);
    scatter_edge_kernel<<<egrid, 256>>>(bufM, bufB, srcp, dstp, dinv, E);
    // layer 2: bufB -> out
    hgemm_kernel<true, false><<<ggrid, 256, SMEM_BYTES>>>(bufB, gwh + 2 * HD * HD, gwl + 2 * HD * HD,
                                                          nullptr, bufM, N, HD);
    scatter_init_kernel<<<(elem4 + 255) / 256, 256>>>(bufM, gb + 2 * HD, dinv, out, N);
    scatter_edge_kernel<<<egrid, 256>>>(bufM, out, srcp, dstp, dinv, E);

    relu_inplace_kernel<<<(elem4 + 255) / 256, 256>>>(out, elem4);
}

// round 14
// speedup vs baseline: 1.8908x; 1.0141x over previous
#include <cuda_runtime.h>
#include <cuda_fp16.h>
#include <cstdint>
#include <cstddef>

// Problem constants
#define NN  100000
#define EE  300000
#define FIN 128
#define HD  256

// ---------------------------------------------------------------------------
// Scratch (allocation-free)
// ---------------------------------------------------------------------------
__device__ float g_bufA[(size_t)NN * HD];
__device__ float g_bufB[(size_t)NN * HD];
__device__ float g_bufM[(size_t)NN * HD];
__device__ int   g_deg[NN];
__device__ float g_dinv[NN];
// Pre-transposed ([N,K]) fp16-split weights
__device__ __half g_w1h[HD * FIN], g_w1l[HD * FIN];
__device__ __half g_w2h[HD * HD],  g_w2l[HD * HD];
__device__ __half g_gwh[3 * HD * HD], g_gwl[3 * HD * HD];

// ---------------------------------------------------------------------------
// Helpers
// ---------------------------------------------------------------------------
static __device__ __forceinline__ uint32_t s2u(const void* p) {
    uint32_t a;
    asm("{ .reg .u64 t; cvta.to.shared.u64 t, %1; cvt.u32.u64 %0, t; }" : "=r"(a) : "l"(p));
    return a;
}

static __device__ __forceinline__ void fsplit(float v, __half& h, __half& l) {
    h = __float2half_rn(v);
    l = __float2half_rn(v - __half2float(h));
}

#define LDSM4(R, addr) \
    asm volatile("ldmatrix.sync.aligned.m8n8.x4.shared.b16 {%0,%1,%2,%3}, [%4];" \
                 : "=r"((R)[0]), "=r"((R)[1]), "=r"((R)[2]), "=r"((R)[3]) : "r"(addr))

#define LDSM2(R, addr) \
    asm volatile("ldmatrix.sync.aligned.m8n8.x2.shared.b16 {%0,%1}, [%2];" \
                 : "=r"((R)[0]), "=r"((R)[1]) : "r"(addr))

#define MMA16816(C, A, B) \
    asm volatile("mma.sync.aligned.m16n8k16.row.col.f32.f16.f16.f32 " \
                 "{%0,%1,%2,%3},{%4,%5,%6,%7},{%8,%9},{%0,%1,%2,%3};" \
                 : "+f"((C)[0]), "+f"((C)[1]), "+f"((C)[2]), "+f"((C)[3]) \
                 : "r"((A)[0]), "r"((A)[1]), "r"((A)[2]), "r"((A)[3]), \
                   "r"((B)[0]), "r"((B)[1]))

#define CPA16(dst, src) \
    asm volatile("cp.async.ca.shared.global [%0], [%1], 16;" :: "r"(dst), "l"(src))

// SMEM geometry (halves). Row stride 40 halves (80B) -> conflict-free ldmatrix.
#define SA 40
#define OFF_AH 0
#define OFF_AL 5120
#define OFF_BH 10240
#define OFF_BL 15360
#define STAGE_H 20480
#define SMEM_BYTES (2 * STAGE_H * 2)

// ---------------------------------------------------------------------------
// fp16x2-split (3-product) tensor-core GEMM:
// C[M,256] = op(A)[M,K] @ Bt[N,K]^T (+bias), op = relu if RELU_A.
// BM=128, BN=128, BK=32, 256 threads. Warps: 2(m) x 4(n); warp tile 64x32.
// FUSE_INIT: also write outp[r,c] = bias[c] + m[r,c]*dinv[r]^2 (GCN self-loop init).
// ---------------------------------------------------------------------------
template<bool RELU_A, bool HAS_BIAS, bool FUSE_INIT>
__global__ __launch_bounds__(256)
void hgemm_kernel(const float* __restrict__ A, const __half* __restrict__ BHp,
                  const __half* __restrict__ BLp, const float* __restrict__ bias,
                  float* __restrict__ C, const float* __restrict__ dinv,
                  float* __restrict__ outp, int M_rows, int K) {
    extern __shared__ __half sh[];
    const int tid  = threadIdx.x;
    const int lane = tid & 31;
    const int wid  = tid >> 5;
    const int wm   = wid & 1;       // 0..1 : 64 rows each
    const int wn   = wid >> 1;      // 0..3 : 32 cols each
    const int block_row = blockIdx.x * 128;
    const int n0        = blockIdx.y * 128;

    float acc[4][4][4];
#pragma unroll
    for (int mt = 0; mt < 4; mt++)
#pragma unroll
        for (int nt = 0; nt < 4; nt++)
#pragma unroll
            for (int j = 0; j < 4; j++) acc[mt][nt][j] = 0.f;

    const int NC = K >> 5;          // chunks of 32

    // Per-thread load coordinates
    const int ar = tid >> 3;                // A row base
    const int ak = (tid & 7) << 2;          // A col group (fp32 x4)
    const int br = tid >> 2;                // B row base
    const int bk = (tid & 3) << 3;          // B col group (half x8)

    float4 apf[4];

#define LOAD_A(c)                                                               \
    {                                                                           \
        const int k0 = (c) << 5;                                                \
        _Pragma("unroll")                                                       \
        for (int i = 0; i < 4; i++) {                                           \
            int row = ar + (i << 5);                                            \
            int gr = block_row + row;                                           \
            if (gr < M_rows)                                                    \
                apf[i] = *(const float4*)(A + (size_t)gr * K + k0 + ak);        \
            else                                                                \
                apf[i] = make_float4(0.f, 0.f, 0.f, 0.f);                       \
        }                                                                       \
    }

#define CPASYNC_B(c, soff)                                                      \
    {                                                                           \
        const int k0 = (c) << 5;                                                \
        _Pragma("unroll")                                                       \
        for (int i = 0; i < 2; i++) {                                           \
            int row = br + (i << 6);                                            \
            size_t g = (size_t)(n0 + row) * K + k0 + bk;                        \
            uint32_t dh = s2u(sh + (soff) + OFF_BH + row * SA + bk);            \
            uint32_t dl = s2u(sh + (soff) + OFF_BL + row * SA + bk);            \
            CPA16(dh, BHp + g);                                                 \
            CPA16(dl, BLp + g);                                                 \
        }                                                                       \
        asm volatile("cp.async.commit_group;");                                 \
    }

#define STORE_A(soff)                                                           \
    {                                                                           \
        _Pragma("unroll")                                                       \
        for (int i = 0; i < 4; i++) {                                           \
            int row = ar + (i << 5);                                            \
            float4 v = apf[i];                                                  \
            if (RELU_A) {                                                       \
                v.x = fmaxf(v.x, 0.f); v.y = fmaxf(v.y, 0.f);                   \
                v.z = fmaxf(v.z, 0.f); v.w = fmaxf(v.w, 0.f);                   \
            }                                                                   \
            __half h0, h1, h2, h3, l0, l1, l2, l3;                              \
            fsplit(v.x, h0, l0); fsplit(v.y, h1, l1);                           \
            fsplit(v.z, h2, l2); fsplit(v.w, h3, l3);                           \
            __half* ph = sh + (soff) + OFF_AH + row * SA + ak;                  \
            __half* pl = sh + (soff) + OFF_AL + row * SA + ak;                  \
            *(__half2*)(ph)     = __halves2half2(h0, h1);                       \
            *(__half2*)(ph + 2) = __halves2half2(h2, h3);                       \
            *(__half2*)(pl)     = __halves2half2(l0, l1);                       \
            *(__half2*)(pl + 2) = __halves2half2(l2, l3);                       \
        }                                                                       \
    }

    // Prologue: fill stage 0
    CPASYNC_B(0, 0);
    LOAD_A(0);
    STORE_A(0);
    asm volatile("cp.async.wait_group 0;");
    __syncthreads();

    for (int c = 0; c < NC; c++) {
        const int soff = (c & 1) * STAGE_H;
        const int nsoff = ((c + 1) & 1) * STAGE_H;
        if (c + 1 < NC) {
            CPASYNC_B(c + 1, nsoff);
            LOAD_A(c + 1);
        }

        // --- MMA on stage soff ---
#pragma unroll
        for (int s = 0; s < 2; s++) {
            uint32_t ah[4][4], al[4][4];
#pragma unroll
            for (int mt = 0; mt < 4; mt++) {
                int row = wm * 64 + mt * 16 + (lane & 15);
                int col = s * 16 + ((lane >> 4) << 3);
                uint32_t ad = s2u(sh + soff + OFF_AH + row * SA + col);
                LDSM4(ah[mt], ad);
                LDSM4(al[mt], ad + OFF_AL * 2);
            }
#pragma unroll
            for (int nt = 0; nt < 4; nt++) {
                int row = wn * 32 + nt * 8 + (lane & 7);
                int col = s * 16 + (((lane >> 3) & 1) << 3);
                uint32_t bd = s2u(sh + soff + OFF_BH + row * SA + col);
                uint32_t bh[2], bl[2];
                LDSM2(bh, bd);
                LDSM2(bl, bd + (OFF_BL - OFF_BH) * 2);
#pragma unroll
                for (int mt = 0; mt < 4; mt++) MMA16816(acc[mt][nt], ah[mt], bh);
#pragma unroll
                for (int mt = 0; mt < 4; mt++) MMA16816(acc[mt][nt], al[mt], bh);
#pragma unroll
                for (int mt = 0; mt < 4; mt++) MMA16816(acc[mt][nt], ah[mt], bl);
            }
        }

        if (c + 1 < NC) {
            STORE_A(nsoff);
            asm volatile("cp.async.wait_group 0;");
            __syncthreads();
        }
    }

    // Epilogue
    const int qm = lane >> 2;          // row within tile
    const int qn = (lane & 3) << 1;    // col pair within n8
#pragma unroll
    for (int mt = 0; mt < 4; mt++) {
        int gr0 = block_row + wm * 64 + mt * 16 + qm;
        int gr1 = gr0 + 8;
        float w0 = 0.f, w1 = 0.f;
        if (FUSE_INIT) {
            if (gr0 < M_rows) { w0 = dinv[gr0]; w0 *= w0; }
            if (gr1 < M_rows) { w1 = dinv[gr1]; w1 *= w1; }
        }
#pragma unroll
        for (int nt = 0; nt < 4; nt++) {
            int nc = n0 + wn * 32 + nt * 8 + qn;
            float b0 = 0.f, b1 = 0.f;
            if (HAS_BIAS || FUSE_INIT) { b0 = bias[nc]; b1 = bias[nc + 1]; }
            if (gr0 < M_rows) {
                float m0 = acc[mt][nt][0], m1 = acc[mt][nt][1];
                if (FUSE_INIT) {
                    *(float2*)(C + (size_t)gr0 * HD + nc) = make_float2(m0, m1);
                    *(float2*)(outp + (size_t)gr0 * HD + nc) =
                        make_float2(fmaf(m0, w0, b0), fmaf(m1, w0, b1));
                } else {
                    *(float2*)(C + (size_t)gr0 * HD + nc) = make_float2(m0 + b0, m1 + b1);
                }
            }
            if (gr1 < M_rows) {
                float m2 = acc[mt][nt][2], m3 = acc[mt][nt][3];
                if (FUSE_INIT) {
                    *(float2*)(C + (size_t)gr1 * HD + nc) = make_float2(m2, m3);
                    *(float2*)(outp + (size_t)gr1 * HD + nc) =
                        make_float2(fmaf(m2, w1, b0), fmaf(m3, w1, b1));
                } else {
                    *(float2*)(C + (size_t)gr1 * HD + nc) = make_float2(m2 + b0, m3 + b1);
                }
            }
        }
    }
#undef LOAD_A
#undef CPASYNC_B
#undef STORE_A
}

// ---------------------------------------------------------------------------
// Combined weight transpose + fp16 split for all 5 matrices.
// w1: [128,256] -> w1h/l [256,128]; w2 + 3x gcn: [256,256] -> [256,256]
// ---------------------------------------------------------------------------
__global__ void wsplit_all_kernel(const float* __restrict__ w1, const float* __restrict__ w2,
                                  const float* __restrict__ gw,
                                  __half* __restrict__ w1h, __half* __restrict__ w1l,
                                  __half* __restrict__ w2h, __half* __restrict__ w2l,
                                  __half* __restrict__ gwh, __half* __restrict__ gwl) {
    int i = blockIdx.x * blockDim.x + threadIdx.x;
    if (i < FIN * HD) {
        int k = i >> 8, n = i & 255;
        __half h, l;
        fsplit(w1[i], h, l);
        w1h[(size_t)n * FIN + k] = h;
        w1l[(size_t)n * FIN + k] = l;
        return;
    }
    int j = i - FIN * HD;
    if (j >= 4 * HD * HD) return;
    int mat = j >> 16;           // 0: w2, 1..3: gcn layers
    int w = j & 65535;
    int k = w >> 8, n = w & 255;
    const float* src = (mat == 0) ? w2 : gw + (size_t)(mat - 1) * HD * HD;
    __half* dh = (mat == 0) ? w2h : gwh + (size_t)(mat - 1) * HD * HD;
    __half* dl = (mat == 0) ? w2l : gwl + (size_t)(mat - 1) * HD * HD;
    __half h, l;
    fsplit(src[w], h, l);
    dh[(size_t)n * HD + k] = h;
    dl[(size_t)n * HD + k] = l;
}

// ---------------------------------------------------------------------------
// Degree / normalization
// ---------------------------------------------------------------------------
__global__ void deg_init_kernel(int* __restrict__ deg, int n) {
    int i = blockIdx.x * blockDim.x + threadIdx.x;
    if (i < n) deg[i] = 1;
}
__global__ void deg_edge_kernel(const int* __restrict__ dst, int* __restrict__ deg, int e) {
    int i = blockIdx.x * blockDim.x + threadIdx.x;
    if (i < e) atomicAdd(&deg[dst[i]], 1);
}
__global__ void dinv_kernel(const int* __restrict__ deg, float* __restrict__ dinv, int n) {
    int i = blockIdx.x * blockDim.x + threadIdx.x;
    if (i < n) dinv[i] = rsqrtf((float)deg[i]);
}

// ---------------------------------------------------------------------------
// Edge scatter: out[dst,:] += m[src,:]*dinv[src]*dinv[dst]
// ---------------------------------------------------------------------------
__device__ __forceinline__ void red_add_v4(float* p, float4 v) {
    asm volatile("red.global.add.v4.f32 [%0], {%1,%2,%3,%4};"
                 :: "l"(p), "f"(v.x), "f"(v.y), "f"(v.z), "f"(v.w) : "memory");
}

__global__ __launch_bounds__(256)
void scatter_edge_kernel(const float* __restrict__ m, float* __restrict__ out,
                         const int* __restrict__ src, const int* __restrict__ dst,
                         const float* __restrict__ dinv, int E) {
    int g = blockIdx.x * blockDim.x + threadIdx.x;
    int e = g >> 5;
    int lane = g & 31;
    if (e >= E) return;
    int s = __ldg(&src[e]);
    int d = __ldg(&dst[e]);
    float w = dinv[s] * dinv[d];
    const float4* mr = (const float4*)(m + (size_t)s * HD);
    float* orow = out + (size_t)d * HD;
    float4 v0 = mr[lane];
    float4 v1 = mr[lane + 32];
    v0.x *= w; v0.y *= w; v0.z *= w; v0.w *= w;
    v1.x *= w; v1.y *= w; v1.z *= w; v1.w *= w;
    red_add_v4(orow + lane * 4, v0);
    red_add_v4(orow + (lane + 32) * 4, v1);
}

__global__ void relu_inplace_kernel(float* __restrict__ p, int total4) {
    int i = blockIdx.x * blockDim.x + threadIdx.x;
    if (i >= total4) return;
    float4 v = ((float4*)p)[i];
    v.x = fmaxf(v.x, 0.f); v.y = fmaxf(v.y, 0.f);
    v.z = fmaxf(v.z, 0.f); v.w = fmaxf(v.w, 0.f);
    ((float4*)p)[i] = v;
}

// ---------------------------------------------------------------------------
// Launch
// ---------------------------------------------------------------------------
extern "C" void kernel_launch(void* const* d_in, const int* in_sizes, int n_in,
                              void* d_out, int out_size) {
    const float* x  = (const float*)d_in[0];
    const int*   ei = (const int*)d_in[1];
    const float* w1 = (const float*)d_in[2];
    const float* b1 = (const float*)d_in[3];
    const float* w2 = (const float*)d_in[4];
    const float* b2 = (const float*)d_in[5];
    const float* gw = (const float*)d_in[6];
    const float* gb = (const float*)d_in[7];

    const int N = NN;
    const int E = EE;
    const int* srcp = ei;
    const int* dstp = ei + E;

    float *bufA, *bufB, *bufM, *dinv;
    __half *w1h, *w1l, *w2h, *w2l, *gwh, *gwl;
    int* deg;
    cudaGetSymbolAddress((void**)&bufA, g_bufA);
    cudaGetSymbolAddress((void**)&bufB, g_bufB);
    cudaGetSymbolAddress((void**)&bufM, g_bufM);
    cudaGetSymbolAddress((void**)&dinv, g_dinv);
    cudaGetSymbolAddress((void**)&deg,  g_deg);
    cudaGetSymbolAddress((void**)&w1h,  g_w1h);
    cudaGetSymbolAddress((void**)&w1l,  g_w1l);
    cudaGetSymbolAddress((void**)&w2h,  g_w2h);
    cudaGetSymbolAddress((void**)&w2l,  g_w2l);
    cudaGetSymbolAddress((void**)&gwh,  g_gwh);
    cudaGetSymbolAddress((void**)&gwl,  g_gwl);

    float* out = (float*)d_out;

    cudaFuncSetAttribute(hgemm_kernel<false, true, false>,
                         cudaFuncAttributeMaxDynamicSharedMemorySize, SMEM_BYTES);
    cudaFuncSetAttribute(hgemm_kernel<true, true, false>,
                         cudaFuncAttributeMaxDynamicSharedMemorySize, SMEM_BYTES);
    cudaFuncSetAttribute(hgemm_kernel<false, false, true>,
                         cudaFuncAttributeMaxDynamicSharedMemorySize, SMEM_BYTES);
    cudaFuncSetAttribute(hgemm_kernel<true, false, true>,
                         cudaFuncAttributeMaxDynamicSharedMemorySize, SMEM_BYTES);

    // Weight transpose + split (single launch)
    {
        int tot = FIN * HD + 4 * HD * HD;
        wsplit_all_kernel<<<(tot + 255) / 256, 256>>>(w1, w2, gw, w1h, w1l, w2h, w2l, gwh, gwl);
    }

    // degrees + normalization
    deg_init_kernel<<<(N + 255) / 256, 256>>>(deg, N);
    deg_edge_kernel<<<(E + 255) / 256, 256>>>(dstp, deg, E);
    dinv_kernel<<<(N + 255) / 256, 256>>>(deg, dinv, N);

    dim3 ggrid((N + 127) / 128, HD / 128);
    const int elem4 = N * (HD / 4);
    const int egrid = (E * 32 + 255) / 256;

    // encoder
    hgemm_kernel<false, true, false><<<ggrid, 256, SMEM_BYTES>>>(
        x, w1h, w1l, b1, bufA, nullptr, nullptr, N, FIN);
    hgemm_kernel<true, true, false><<<ggrid, 256, SMEM_BYTES>>>(
        bufA, w2h, w2l, b2, bufB, nullptr, nullptr, N, HD);

    // GCN layer 0: h=bufB -> m=bufM, init out=bufA; edges into bufA
    hgemm_kernel<false, false, true><<<ggrid, 256, SMEM_BYTES>>>(
        bufB, gwh, gwl, gb + 0 * HD, bufM, dinv, bufA, N, HD);
    scatter_edge_kernel<<<egrid, 256>>>(bufM, bufA, srcp, dstp, dinv, E);
    // layer 1: h=bufA (deferred relu) -> m=bufM, init out=bufB
    hgemm_kernel<true, false, true><<<ggrid, 256, SMEM_BYTES>>>(
        bufA, gwh + HD * HD, gwl + HD * HD, gb + 1 * HD, bufM, dinv, bufB, N, HD);
    scatter_edge_kernel<<<egrid, 256>>>(bufM, bufB, srcp, dstp, dinv, E);
    // layer 2: h=bufB -> m=bufM, init out=d_out
    hgemm_kernel<true, false, true><<<ggrid, 256, SMEM_BYTES>>>(
        bufB, gwh + 2 * HD * HD, gwl + 2 * HD * HD, gb + 2 * HD, bufM, dinv, out, N, HD);
    scatter_edge_kernel<<<egrid, 256>>>(bufM, out, srcp, dstp, dinv, E);

    relu_inplace_kernel<<<(elem4 + 255) / 256, 256>>>(out, elem4);
}